// round 5
// baseline (speedup 1.0000x reference)
#include <cuda_runtime.h>
#include <cuda_bf16.h>
#include <cstdint>

#define B 8
#define S 2048
#define H 2048
#define A 8192

// output section offsets (element counts, float32)
#define OUT0 0ULL                               // x*best_path  [B*S*H]
#define OUT1 (OUT0 + (size_t)B * S * H)         // new_trails   [H*H]
#define OUT2 (OUT1 + (size_t)H * H)             // new_paths    [A*H]
#define OUT3 (OUT2 + (size_t)A * H)             // new_best_len [1]
#define OUT4 (OUT3 + 1ULL)                      // next_pos     [A] (as f32)

#define TRAIL_BLOCKS (H * H / 4 / 256 / 2)          // 2048 (2 float4/thread)
#define OUT_BLOCKS   ((B * S * H) / 4 / 256 / 4)    // 8192  (4 float4/thread)

// ---------------- device scratch (no allocations allowed) ----------------
__device__ float g_len[A];
__device__ float g_diag[H];
__device__ float g_bestpath[H];
__device__ float g_rowmax[H];
__device__ float g_rowlse[H];
__device__ int   g_rowconst[H];
__device__ volatile uint32_t g_one = 1u;   // opaque 1: forces adds onto IMAD (fma pipe)

// ---------------- threefry2x32, key = (0, 42) ----------------
// adds written as one*a + b so ptxas emits IMAD (fma pipe), leaving the alu
// pipe for SHF/LOP3 — threefry is alu-pipe-bound otherwise.
__device__ __forceinline__ void threefry_0_42(uint32_t one, uint32_t x0, uint32_t x1,
                                              uint32_t& o0, uint32_t& o1) {
    const uint32_t k0 = 0u, k1 = 42u;
    const uint32_t k2 = k0 ^ k1 ^ 0x1BD11BDAu;
    x0 = one * x0 + k0; x1 = one * x1 + k1;
#define TF_R(r) { x0 = one * x1 + x0; x1 = __funnelshift_l(x1, x1, (r)); x1 ^= x0; }
    TF_R(13) TF_R(15) TF_R(26) TF_R(6)
    x0 = one * k1 + x0; x1 = one * (k2 + 1u) + x1;
    TF_R(17) TF_R(29) TF_R(16) TF_R(24)
    x0 = one * k2 + x0; x1 = one * (k0 + 2u) + x1;
    TF_R(13) TF_R(15) TF_R(26) TF_R(6)
    x0 = one * k0 + x0; x1 = one * (k1 + 3u) + x1;
    TF_R(17) TF_R(29) TF_R(16) TF_R(24)
    x0 = one * k1 + x0; x1 = one * (k2 + 4u) + x1;
    TF_R(13) TF_R(15) TF_R(26) TF_R(6)
    x0 = one * k2 + x0; x1 = one * (k0 + 5u) + x1;
#undef TF_R
    o0 = x0; o1 = x1;
}

// partitionable threefry: counter = (0, i), bits = out0 ^ out1
__device__ __forceinline__ uint32_t random_bits_partitionable(uint32_t one, uint32_t i) {
    uint32_t o0, o1;
    threefry_0_42(one, 0u, i, o0, o1);
    return o0 ^ o1;
}

__device__ __forceinline__ float gumbel_from_bits(uint32_t bits) {
    float f = __uint_as_float((bits >> 9) | 0x3F800000u) - 1.0f;
    const float tiny = 1.17549435e-38f;
    float u = fmaxf(tiny, f * (1.0f - tiny) + tiny);
    float t = -__logf(u);
    return -__logf(t);
}

// ---------------- K0: row max/lse/const-flag of trails; zero diag ----------
__global__ void k0_rowstats(const float* __restrict__ trails) {
    __shared__ float smax[256];
    __shared__ float smin[256];
    int r = blockIdx.x;
    int tid = threadIdx.x;
    const float* row = trails + (size_t)r * H;
    float m = -__int_as_float(0x7f800000);
    float mn = __int_as_float(0x7f800000);
    #pragma unroll
    for (int k = 0; k < H / 256; k++) {
        float v = row[tid + k * 256];
        m = fmaxf(m, v); mn = fminf(mn, v);
    }
    smax[tid] = m; smin[tid] = mn; __syncthreads();
    for (int s = 128; s > 0; s >>= 1) {
        if (tid < s) {
            smax[tid] = fmaxf(smax[tid], smax[tid + s]);
            smin[tid] = fminf(smin[tid], smin[tid + s]);
        }
        __syncthreads();
    }
    float rmax = smax[0], rmin = smin[0]; __syncthreads();
    float sum = 0.0f;
    #pragma unroll
    for (int k = 0; k < H / 256; k++) sum += expf(row[tid + k * 256] - rmax);
    smax[tid] = sum; __syncthreads();
    for (int s = 128; s > 0; s >>= 1) {
        if (tid < s) smax[tid] += smax[tid + s];
        __syncthreads();
    }
    if (tid == 0) {
        g_rowmax[r] = rmax;
        g_rowlse[r] = logf(smax[0]);
        g_rowconst[r] = (rmax == rmin);
        g_diag[r] = 0.0f;
    }
}

// ---------------- K12: fused sampling + paths + lengths + diag -------------
__global__ void k12_sample_paths(const float* __restrict__ trails,
                                 const float* __restrict__ ant_paths,
                                 const int* __restrict__ ant_positions,
                                 const float* __restrict__ strength_p,
                                 float* __restrict__ out2,
                                 float* __restrict__ out4) {
    __shared__ float sv[256];
    __shared__ int   si[256];
    __shared__ float ss[256];
    __shared__ float s_upd;
    __shared__ int   s_np;
    int a = blockIdx.x;
    int tid = threadIdx.x;
    int p = ant_positions[a];
    const float* prow = ant_paths + (size_t)a * H;
    uint32_t one = g_one;   // opaque 1 (volatile load)

    float v[H / 256];
    float sumsq = 0.0f;
    float bvf = -__int_as_float(0x7f800000);
    int   bi = 0;

    if (g_rowconst[p]) {
        // constant logits: argmax z == argmax (bits>>9), compared as uint.
        // Identical ordering AND tie structure vs the reference f32 compare
        // (23-bit values are exact in f32); first-index tie-break preserved.
        uint32_t bvu = 0u;
        #pragma unroll
        for (int k = 0; k < H / 256; k++) {
            int h = k * 256 + tid;
            uint32_t bits = random_bits_partitionable(one, (uint32_t)a * H + (uint32_t)h);
            uint32_t z = bits >> 9;
            if (z > bvu) { bvu = z; bi = h; }   // h increasing -> first index kept
            float pv = prow[h];
            v[k] = pv;
            sumsq += pv * pv;
        }
        bvf = (float)bvu;   // exact (23-bit)
    } else {
        const float* trow = trails + (size_t)p * H;
        float rm = g_rowmax[p], rl = g_rowlse[p];
        #pragma unroll
        for (int k = 0; k < H / 256; k++) {
            int h = k * 256 + tid;
            uint32_t bits = random_bits_partitionable(one, (uint32_t)a * H + (uint32_t)h);
            float z = gumbel_from_bits(bits) + ((trow[h] - rm) - rl);
            if (z > bvf) { bvf = z; bi = h; }
            float pv = prow[h];
            v[k] = pv;
            sumsq += pv * pv;
        }
    }

    sv[tid] = bvf; si[tid] = bi; ss[tid] = sumsq; __syncthreads();
    for (int s = 128; s > 0; s >>= 1) {
        if (tid < s) {
            float v2 = sv[tid + s]; int i2 = si[tid + s];
            if (v2 > sv[tid] || (v2 == sv[tid] && i2 < si[tid])) { sv[tid] = v2; si[tid] = i2; }
            ss[tid] += ss[tid + s];
        }
        __syncthreads();
    }
    if (tid == 0) {
        int np = si[0];
        float old = prow[np];
        float len = sqrtf(ss[0] - old * old + 1.0f);   // one-hot substitution
        g_len[a] = len;
        s_np = np;
        s_upd = strength_p[0] / (len + 1e-8f);
        out4[a] = (float)np;
    }
    __syncthreads();
    int np = s_np;
    float upd = s_upd;
    // loop2: write new_paths from registers + diag scatter
    #pragma unroll
    for (int k = 0; k < H / 256; k++) {
        int h = k * 256 + tid;
        float pv = v[k];
        if (h == np) pv = 1.0f;
        out2[(size_t)a * H + h] = pv;
        if (pv > 0.0f) atomicAdd(&g_diag[h], upd);
    }
}

// ---------------- K34: argmin + best path materialization (1 block) --------
__global__ void k34_best(const float* __restrict__ bpl_p,
                         const float* __restrict__ best_path_in,
                         const float* __restrict__ new_paths_out,
                         float* __restrict__ out3) {
    __shared__ float sv[1024];
    __shared__ int   si[1024];
    __shared__ int   s_best, s_imp;
    int tid = threadIdx.x;
    float bv = __int_as_float(0x7f800000); int bi = 0;
    for (int a = tid; a < A; a += 1024) {
        float v = g_len[a];
        if (v < bv) { bv = v; bi = a; }     // ascending a => first index kept
    }
    sv[tid] = bv; si[tid] = bi; __syncthreads();
    for (int s = 512; s > 0; s >>= 1) {
        if (tid < s) {
            float v2 = sv[tid + s]; int i2 = si[tid + s];
            if (v2 < sv[tid] || (v2 == sv[tid] && i2 < si[tid])) { sv[tid] = v2; si[tid] = i2; }
        }
        __syncthreads();
    }
    if (tid == 0) {
        float bpl = bpl_p[0];
        int improved = sv[0] < bpl;
        s_best = si[0];
        s_imp = improved;
        out3[0] = improved ? sv[0] : bpl;
    }
    __syncthreads();
    int best = s_best, imp = s_imp;
    for (int h = tid; h < H; h += 1024) {
        g_bestpath[h] = imp ? new_paths_out[(size_t)best * H + h] : best_path_in[h];
    }
}

// ---------------- K56: trails update + broadcast multiply (one launch) -----
__global__ void k56_finish(const float* __restrict__ trails,
                           const float* __restrict__ decay_p,
                           const float* __restrict__ x,
                           float* __restrict__ out1,
                           float* __restrict__ out0) {
    int b = blockIdx.x;
    int tid = threadIdx.x;
    if (b < TRAIL_BLOCKS) {
        float dec = 1.0f - decay_p[0];
        size_t base = (size_t)b * 256 + tid;
        #pragma unroll
        for (int j = 0; j < 2; j++) {
            size_t idx4 = (base + (size_t)j * TRAIL_BLOCKS * 256) * 4;
            int i  = (int)(idx4 >> 11);       // row
            int j0 = (int)(idx4 & (H - 1));
            const float4 t = *reinterpret_cast<const float4*>(trails + idx4);
            float d = g_diag[i];
            float4 o;
            o.x = (t.x + (i == (j0 + 0) ? d : 0.0f)) * dec;
            o.y = (t.y + (i == (j0 + 1) ? d : 0.0f)) * dec;
            o.z = (t.z + (i == (j0 + 2) ? d : 0.0f)) * dec;
            o.w = (t.w + (i == (j0 + 3) ? d : 0.0f)) * dec;
            *reinterpret_cast<float4*>(out1 + idx4) = o;
        }
    } else {
        // x section: 4 independent float4 per thread, front-batched loads
        size_t base = (size_t)(b - TRAIL_BLOCKS) * 256 + tid;
        size_t idx[4];
        float4 xv[4];
        #pragma unroll
        for (int j = 0; j < 4; j++) {
            idx[j] = (base + (size_t)j * OUT_BLOCKS * 256) * 4;
            xv[j] = *reinterpret_cast<const float4*>(x + idx[j]);
        }
        #pragma unroll
        for (int j = 0; j < 4; j++) {
            int h0 = (int)(idx[j] & (H - 1));
            float4 o;
            o.x = xv[j].x * g_bestpath[h0 + 0];
            o.y = xv[j].y * g_bestpath[h0 + 1];
            o.z = xv[j].z * g_bestpath[h0 + 2];
            o.w = xv[j].w * g_bestpath[h0 + 3];
            *reinterpret_cast<float4*>(out0 + idx[j]) = o;
        }
    }
}

extern "C" void kernel_launch(void* const* d_in, const int* in_sizes, int n_in,
                              void* d_out, int out_size) {
    const float* x        = (const float*)d_in[0];
    const float* trails   = (const float*)d_in[1];
    const float* paths    = (const float*)d_in[2];
    const float* bestpath = (const float*)d_in[3];
    const float* bpl      = (const float*)d_in[4];
    const float* decay    = (const float*)d_in[5];
    const float* strength = (const float*)d_in[6];
    const int*   antpos   = (const int*)d_in[7];
    float* out = (float*)d_out;

    k0_rowstats<<<H, 256>>>(trails);
    k12_sample_paths<<<A, 256>>>(trails, paths, antpos, strength,
                                 out + OUT2, out + OUT4);
    k34_best<<<1, 1024>>>(bpl, bestpath, out + OUT2, out + OUT3);
    k56_finish<<<TRAIL_BLOCKS + OUT_BLOCKS, 256>>>(trails, decay, x,
                                                   out + OUT1, out + OUT0);
}

// round 6
// speedup vs baseline: 1.2497x; 1.2497x over previous
#include <cuda_runtime.h>
#include <cuda_bf16.h>
#include <cstdint>

#define B 8
#define S 2048
#define H 2048
#define A 8192

// output section offsets (element counts, float32)
#define OUT0 0ULL                               // x*best_path  [B*S*H]
#define OUT1 (OUT0 + (size_t)B * S * H)         // new_trails   [H*H]
#define OUT2 (OUT1 + (size_t)H * H)             // new_paths    [A*H]
#define OUT3 (OUT2 + (size_t)A * H)             // new_best_len [1]
#define OUT4 (OUT3 + 1ULL)                      // next_pos     [A] (as f32)

#define TRAIL_BLOCKS (H * H / 4 / 256 / 2)          // 2048 (2 float4/thread)
#define OUT_BLOCKS   ((B * S * H) / 4 / 256 / 4)    // 8192  (4 float4/thread)

// ---------------- device scratch (no allocations allowed) ----------------
__device__ float g_len_unused[1];
__device__ float g_diag[H];
__device__ __align__(16) float g_bestpath[H];
__device__ float g_rowmax[H];
__device__ float g_rowlse[H];
__device__ int   g_rowconst[H];
__device__ unsigned long long g_minkey;   // (len_bits<<32)|ant : atomicMin argmin

// ---------------- threefry2x32, key = (0, 42) ----------------
__device__ __forceinline__ void threefry_0_42(uint32_t x0, uint32_t x1,
                                              uint32_t& o0, uint32_t& o1) {
    const uint32_t k0 = 0u, k1 = 42u;
    const uint32_t k2 = k0 ^ k1 ^ 0x1BD11BDAu;
    x0 += k0; x1 += k1;
#define TF_R(r) { x0 += x1; x1 = __funnelshift_l(x1, x1, (r)); x1 ^= x0; }
    TF_R(13) TF_R(15) TF_R(26) TF_R(6)
    x0 += k1; x1 += k2 + 1u;
    TF_R(17) TF_R(29) TF_R(16) TF_R(24)
    x0 += k2; x1 += k0 + 2u;
    TF_R(13) TF_R(15) TF_R(26) TF_R(6)
    x0 += k0; x1 += k1 + 3u;
    TF_R(17) TF_R(29) TF_R(16) TF_R(24)
    x0 += k1; x1 += k2 + 4u;
    TF_R(13) TF_R(15) TF_R(26) TF_R(6)
    x0 += k2; x1 += k0 + 5u;
#undef TF_R
    o0 = x0; o1 = x1;
}

// partitionable threefry: counter = (0, i), bits = out0 ^ out1
__device__ __forceinline__ uint32_t random_bits_partitionable(uint32_t i) {
    uint32_t o0, o1;
    threefry_0_42(0u, i, o0, o1);
    return o0 ^ o1;
}

__device__ __forceinline__ float gumbel_from_bits(uint32_t bits) {
    float f = __uint_as_float((bits >> 9) | 0x3F800000u) - 1.0f;
    const float tiny = 1.17549435e-38f;
    float u = fmaxf(tiny, f * (1.0f - tiny) + tiny);
    float t = -__logf(u);
    return -__logf(t);
}

// ---------------- K0: row max/lse/const-flag of trails; zero diag ----------
__global__ void k0_rowstats(const float* __restrict__ trails) {
    __shared__ float smax[256];
    __shared__ float smin[256];
    int r = blockIdx.x;
    int tid = threadIdx.x;
    const float* row = trails + (size_t)r * H;
    float m = -__int_as_float(0x7f800000);
    float mn = __int_as_float(0x7f800000);
    #pragma unroll
    for (int k = 0; k < H / 256; k++) {
        float v = row[tid + k * 256];
        m = fmaxf(m, v); mn = fminf(mn, v);
    }
    smax[tid] = m; smin[tid] = mn; __syncthreads();
    for (int s = 128; s > 0; s >>= 1) {
        if (tid < s) {
            smax[tid] = fmaxf(smax[tid], smax[tid + s]);
            smin[tid] = fminf(smin[tid], smin[tid + s]);
        }
        __syncthreads();
    }
    float rmax = smax[0], rmin = smin[0]; __syncthreads();
    float sum = 0.0f;
    #pragma unroll
    for (int k = 0; k < H / 256; k++) sum += expf(row[tid + k * 256] - rmax);
    smax[tid] = sum; __syncthreads();
    for (int s = 128; s > 0; s >>= 1) {
        if (tid < s) smax[tid] += smax[tid + s];
        __syncthreads();
    }
    if (tid == 0) {
        g_rowmax[r] = rmax;
        g_rowlse[r] = logf(smax[0]);
        g_rowconst[r] = (rmax == rmin);
        g_diag[r] = 0.0f;
        if (r == 0) g_minkey = ~0ULL;   // reset argmin key each launch
    }
}

// ---------------- K12: fused sampling + paths + lengths + diag + argmin ----
__global__ void k12_sample_paths(const float* __restrict__ trails,
                                 const float* __restrict__ ant_paths,
                                 const int* __restrict__ ant_positions,
                                 const float* __restrict__ strength_p,
                                 float* __restrict__ out2,
                                 float* __restrict__ out4) {
    __shared__ float sv[256];
    __shared__ int   si[256];
    __shared__ float ss[256];
    __shared__ float s_upd;
    __shared__ int   s_np;
    int a = blockIdx.x;
    int tid = threadIdx.x;
    int p = ant_positions[a];
    const float* prow = ant_paths + (size_t)a * H;

    float v[H / 256];
    float sumsq = 0.0f;
    float bvf = -__int_as_float(0x7f800000);
    int   bi = 0;

    if (g_rowconst[p]) {
        // constant logits: argmax z == argmax (bits>>9), compared as uint.
        // Ordering AND tie structure identical to the reference f32 compare.
        uint32_t bvu = 0u;
        #pragma unroll
        for (int k = 0; k < H / 256; k++) {
            int h = k * 256 + tid;
            uint32_t bits = random_bits_partitionable((uint32_t)a * H + (uint32_t)h);
            uint32_t z = bits >> 9;
            if (z > bvu) { bvu = z; bi = h; }   // h increasing -> first index kept
            float pv = prow[h];
            v[k] = pv;
            sumsq += pv * pv;
        }
        bvf = (float)bvu;   // exact (23-bit)
    } else {
        const float* trow = trails + (size_t)p * H;
        float rm = g_rowmax[p], rl = g_rowlse[p];
        #pragma unroll
        for (int k = 0; k < H / 256; k++) {
            int h = k * 256 + tid;
            uint32_t bits = random_bits_partitionable((uint32_t)a * H + (uint32_t)h);
            float z = gumbel_from_bits(bits) + ((trow[h] - rm) - rl);
            if (z > bvf) { bvf = z; bi = h; }
            float pv = prow[h];
            v[k] = pv;
            sumsq += pv * pv;
        }
    }

    sv[tid] = bvf; si[tid] = bi; ss[tid] = sumsq; __syncthreads();
    for (int s = 128; s > 0; s >>= 1) {
        if (tid < s) {
            float v2 = sv[tid + s]; int i2 = si[tid + s];
            if (v2 > sv[tid] || (v2 == sv[tid] && i2 < si[tid])) { sv[tid] = v2; si[tid] = i2; }
            ss[tid] += ss[tid + s];
        }
        __syncthreads();
    }
    if (tid == 0) {
        int np = si[0];
        float old = prow[np];
        float len = sqrtf(ss[0] - old * old + 1.0f);   // one-hot substitution
        // global argmin: len>=0 so float order == uint bit order; low word = ant
        // -> min key gives min length with FIRST index on ties (matches argmin)
        unsigned long long key =
            ((unsigned long long)__float_as_uint(len) << 32) | (unsigned)a;
        atomicMin(&g_minkey, key);
        s_np = np;
        s_upd = strength_p[0] / (len + 1e-8f);
        out4[a] = (float)np;
    }
    __syncthreads();
    int np = s_np;
    float upd = s_upd;
    // loop2: write new_paths from registers + diag scatter
    #pragma unroll
    for (int k = 0; k < H / 256; k++) {
        int h = k * 256 + tid;
        float pv = v[k];
        if (h == np) pv = 1.0f;
        out2[(size_t)a * H + h] = pv;
        if (pv > 0.0f) atomicAdd(&g_diag[h], upd);
    }
}

// ---------------- K34: finalize best len + materialize best path ----------
__global__ void k34_best(const float* __restrict__ bpl_p,
                         const float* __restrict__ best_path_in,
                         const float* __restrict__ new_paths_out,
                         float* __restrict__ out3) {
    int tid = threadIdx.x;
    unsigned long long key = g_minkey;
    float blen = __uint_as_float((unsigned)(key >> 32));
    int   best = (int)(unsigned)(key & 0xFFFFFFFFu);
    float bpl  = bpl_p[0];
    int improved = blen < bpl;
    if (tid == 0) out3[0] = improved ? blen : bpl;
    const float* src = improved ? (new_paths_out + (size_t)best * H) : best_path_in;
    for (int h = tid; h < H; h += 1024) g_bestpath[h] = src[h];
}

// ---------------- K56: trails update + broadcast multiply (one launch) -----
__global__ void k56_finish(const float* __restrict__ trails,
                           const float* __restrict__ decay_p,
                           const float* __restrict__ x,
                           float* __restrict__ out1,
                           float* __restrict__ out0) {
    int b = blockIdx.x;
    int tid = threadIdx.x;
    if (b < TRAIL_BLOCKS) {
        float dec = 1.0f - decay_p[0];
        size_t base = (size_t)b * 256 + tid;
        #pragma unroll
        for (int j = 0; j < 2; j++) {
            size_t idx4 = (base + (size_t)j * TRAIL_BLOCKS * 256) * 4;
            int i  = (int)(idx4 >> 11);       // row
            int j0 = (int)(idx4 & (H - 1));
            const float4 t = *reinterpret_cast<const float4*>(trails + idx4);
            float d = g_diag[i];
            float4 o;
            o.x = (t.x + (i == (j0 + 0) ? d : 0.0f)) * dec;
            o.y = (t.y + (i == (j0 + 1) ? d : 0.0f)) * dec;
            o.z = (t.z + (i == (j0 + 2) ? d : 0.0f)) * dec;
            o.w = (t.w + (i == (j0 + 3) ? d : 0.0f)) * dec;
            *reinterpret_cast<float4*>(out1 + idx4) = o;
        }
    } else {
        // x section: 4 float4/thread; skip reading x where bestpath chunk == 0
        size_t base = (size_t)(b - TRAIL_BLOCKS) * 256 + tid;
        #pragma unroll
        for (int j = 0; j < 4; j++) {
            size_t idx4 = (base + (size_t)j * OUT_BLOCKS * 256) * 4;
            int h0 = (int)(idx4 & (H - 1));
            const float4 bp = *reinterpret_cast<const float4*>(g_bestpath + h0);
            float4 o = make_float4(0.0f, 0.0f, 0.0f, 0.0f);
            if (bp.x != 0.0f || bp.y != 0.0f || bp.z != 0.0f || bp.w != 0.0f) {
                const float4 xv = *reinterpret_cast<const float4*>(x + idx4);
                o.x = xv.x * bp.x;
                o.y = xv.y * bp.y;
                o.z = xv.z * bp.z;
                o.w = xv.w * bp.w;
            }
            *reinterpret_cast<float4*>(out0 + idx4) = o;
        }
    }
}

extern "C" void kernel_launch(void* const* d_in, const int* in_sizes, int n_in,
                              void* d_out, int out_size) {
    const float* x        = (const float*)d_in[0];
    const float* trails   = (const float*)d_in[1];
    const float* paths    = (const float*)d_in[2];
    const float* bestpath = (const float*)d_in[3];
    const float* bpl      = (const float*)d_in[4];
    const float* decay    = (const float*)d_in[5];
    const float* strength = (const float*)d_in[6];
    const int*   antpos   = (const int*)d_in[7];
    float* out = (float*)d_out;

    k0_rowstats<<<H, 256>>>(trails);
    k12_sample_paths<<<A, 256>>>(trails, paths, antpos, strength,
                                 out + OUT2, out + OUT4);
    k34_best<<<1, 1024>>>(bpl, bestpath, out + OUT2, out + OUT3);
    k56_finish<<<TRAIL_BLOCKS + OUT_BLOCKS, 256>>>(trails, decay, x,
                                                   out + OUT1, out + OUT0);
}

// round 7
// speedup vs baseline: 1.2762x; 1.0211x over previous
#include <cuda_runtime.h>
#include <cuda_bf16.h>
#include <cstdint>

#define B 8
#define S 2048
#define H 2048
#define A 8192

// output section offsets (element counts, float32)
#define OUT0 0ULL                               // x*best_path  [B*S*H]
#define OUT1 (OUT0 + (size_t)B * S * H)         // new_trails   [H*H]
#define OUT2 (OUT1 + (size_t)H * H)             // new_paths    [A*H]
#define OUT3 (OUT2 + (size_t)A * H)             // new_best_len [1]
#define OUT4 (OUT3 + 1ULL)                      // next_pos     [A] (as f32)

#define TRAIL_BLOCKS (H * H / 4 / 256 / 2)          // 2048 (2 float4/thread)
#define OUT_BLOCKS   ((B * S * H) / 4 / 256 / 4)    // 8192  (4 float4/thread)

// ---------------- device scratch (no allocations allowed) ----------------
__device__ float g_diag[H];
__device__ __align__(16) float g_bestpath[H];
__device__ float g_rowmax[H];
__device__ float g_rowlse[H];
__device__ int   g_rowconst[H];
__device__ unsigned long long g_minkey;   // (len_bits<<32)|ant : atomicMin argmin

// ---------------- threefry2x32, key = (0, 42) ----------------
__device__ __forceinline__ void threefry_0_42(uint32_t x0, uint32_t x1,
                                              uint32_t& o0, uint32_t& o1) {
    const uint32_t k0 = 0u, k1 = 42u;
    const uint32_t k2 = k0 ^ k1 ^ 0x1BD11BDAu;
    x0 += k0; x1 += k1;
#define TF_R(r) { x0 += x1; x1 = __funnelshift_l(x1, x1, (r)); x1 ^= x0; }
    TF_R(13) TF_R(15) TF_R(26) TF_R(6)
    x0 += k1; x1 += k2 + 1u;
    TF_R(17) TF_R(29) TF_R(16) TF_R(24)
    x0 += k2; x1 += k0 + 2u;
    TF_R(13) TF_R(15) TF_R(26) TF_R(6)
    x0 += k0; x1 += k1 + 3u;
    TF_R(17) TF_R(29) TF_R(16) TF_R(24)
    x0 += k1; x1 += k2 + 4u;
    TF_R(13) TF_R(15) TF_R(26) TF_R(6)
    x0 += k2; x1 += k0 + 5u;
#undef TF_R
    o0 = x0; o1 = x1;
}

// partitionable threefry: counter = (0, i), bits = out0 ^ out1
__device__ __forceinline__ uint32_t random_bits_partitionable(uint32_t i) {
    uint32_t o0, o1;
    threefry_0_42(0u, i, o0, o1);
    return o0 ^ o1;
}

__device__ __forceinline__ float gumbel_from_bits(uint32_t bits) {
    float f = __uint_as_float((bits >> 9) | 0x3F800000u) - 1.0f;
    const float tiny = 1.17549435e-38f;
    float u = fmaxf(tiny, f * (1.0f - tiny) + tiny);
    float t = -__logf(u);
    return -__logf(t);
}

// ---------------- K0: row max/lse/const-flag of trails; zero diag ----------
__global__ void k0_rowstats(const float* __restrict__ trails) {
    __shared__ float smax[256];
    __shared__ float smin[256];
    int r = blockIdx.x;
    int tid = threadIdx.x;
    const float* row = trails + (size_t)r * H;
    float m = -__int_as_float(0x7f800000);
    float mn = __int_as_float(0x7f800000);
    #pragma unroll
    for (int k = 0; k < H / 256; k++) {
        float v = row[tid + k * 256];
        m = fmaxf(m, v); mn = fminf(mn, v);
    }
    smax[tid] = m; smin[tid] = mn; __syncthreads();
    for (int s = 128; s > 0; s >>= 1) {
        if (tid < s) {
            smax[tid] = fmaxf(smax[tid], smax[tid + s]);
            smin[tid] = fminf(smin[tid], smin[tid + s]);
        }
        __syncthreads();
    }
    float rmax = smax[0], rmin = smin[0]; __syncthreads();
    float sum = 0.0f;
    #pragma unroll
    for (int k = 0; k < H / 256; k++) sum += expf(row[tid + k * 256] - rmax);
    smax[tid] = sum; __syncthreads();
    for (int s = 128; s > 0; s >>= 1) {
        if (tid < s) smax[tid] += smax[tid + s];
        __syncthreads();
    }
    if (tid == 0) {
        g_rowmax[r] = rmax;
        g_rowlse[r] = logf(smax[0]);
        g_rowconst[r] = (rmax == rmin);
        g_diag[r] = 0.0f;
        if (r == 0) g_minkey = ~0ULL;   // reset argmin key each launch
    }
}

// ---------------- K12: fused sampling + paths + lengths + diag + argmin ----
__global__ void __launch_bounds__(256)
k12_sample_paths(const float* __restrict__ trails,
                 const float* __restrict__ ant_paths,
                 const int* __restrict__ ant_positions,
                 const float* __restrict__ strength_p,
                 float* __restrict__ out2,
                 float* __restrict__ out4) {
    __shared__ float sv[256];
    __shared__ int   si[256];
    __shared__ float ss[256];
    __shared__ float s_upd;
    __shared__ int   s_np;
    int a = blockIdx.x;
    int tid = threadIdx.x;
    int p = ant_positions[a];
    const float* prow = ant_paths + (size_t)a * H;
    float* orow = out2 + (size_t)a * H;

    float sumsq = 0.0f;
    float bvf;
    int   bi;
    uint32_t mask = 0;   // bit k set <=> prow[k*256+tid] > 0

    if (g_rowconst[p]) {
        // constant logits: argmax z == argmax (bits>>9), done as packed uint
        // max: w = (z<<3)|(7-k) -> max w == max z with smallest k on ties
        // (exact: z ordering and tie structure match the reference f32 path).
        uint32_t bw = 0u;
        #pragma unroll
        for (uint32_t k = 0; k < H / 256; k++) {
            int h = k * 256 + tid;
            uint32_t bits = random_bits_partitionable((uint32_t)a * H + (uint32_t)h);
            uint32_t w = ((bits >> 6) & 0x03FFFFF8u) | (7u - k);
            bw = max(bw, w);
            float pv = prow[h];
            orow[h] = pv;                     // store under ALU shadow
            if (pv > 0.0f) mask |= 1u << k;
            sumsq += pv * pv;
        }
        bvf = (float)(bw >> 3);               // exact (23-bit)
        bi  = (int)(7u - (bw & 7u)) * 256 + tid;
    } else {
        const float* trow = trails + (size_t)p * H;
        float rm = g_rowmax[p], rl = g_rowlse[p];
        bvf = -__int_as_float(0x7f800000); bi = 0;
        #pragma unroll
        for (uint32_t k = 0; k < H / 256; k++) {
            int h = k * 256 + tid;
            uint32_t bits = random_bits_partitionable((uint32_t)a * H + (uint32_t)h);
            float z = gumbel_from_bits(bits) + ((trow[h] - rm) - rl);
            if (z > bvf) { bvf = z; bi = h; }  // h increasing -> first index kept
            float pv = prow[h];
            orow[h] = pv;
            if (pv > 0.0f) mask |= 1u << k;
            sumsq += pv * pv;
        }
    }

    sv[tid] = bvf; si[tid] = bi; ss[tid] = sumsq; __syncthreads();
    for (int s = 128; s > 0; s >>= 1) {
        if (tid < s) {
            float v2 = sv[tid + s]; int i2 = si[tid + s];
            if (v2 > sv[tid] || (v2 == sv[tid] && i2 < si[tid])) { sv[tid] = v2; si[tid] = i2; }
            ss[tid] += ss[tid + s];
        }
        __syncthreads();
    }
    if (tid == 0) {
        int np = si[0];
        float old = prow[np];
        float len = sqrtf(ss[0] - old * old + 1.0f);   // one-hot substitution
        // global argmin: len>=0 -> float order == uint bit order; low word = ant
        unsigned long long key =
            ((unsigned long long)__float_as_uint(len) << 32) | (unsigned)a;
        atomicMin(&g_minkey, key);
        s_np = np;
        s_upd = strength_p[0] / (len + 1e-8f);
        out4[a] = (float)np;
    }
    __syncthreads();
    float upd = s_upd;
    int np = s_np;
    // sparse fixups only (stores already done in loop1)
    if (mask) {
        #pragma unroll
        for (uint32_t k = 0; k < H / 256; k++)
            if (mask & (1u << k)) atomicAdd(&g_diag[k * 256 + tid], upd);
    }
    if (tid == 0) {
        orow[np] = 1.0f;                       // after __syncthreads: ordered
        if (!(prow[np] > 0.0f)) atomicAdd(&g_diag[np], upd);
    }
}

// ---------------- K34: finalize best len + materialize best path ----------
__global__ void k34_best(const float* __restrict__ bpl_p,
                         const float* __restrict__ best_path_in,
                         const float* __restrict__ new_paths_out,
                         float* __restrict__ out3) {
    int tid = threadIdx.x;
    unsigned long long key = g_minkey;
    float blen = __uint_as_float((unsigned)(key >> 32));
    int   best = (int)(unsigned)(key & 0xFFFFFFFFu);
    float bpl  = bpl_p[0];
    int improved = blen < bpl;
    if (tid == 0) out3[0] = improved ? blen : bpl;
    const float* src = improved ? (new_paths_out + (size_t)best * H) : best_path_in;
    for (int h = tid; h < H; h += 1024) g_bestpath[h] = src[h];
}

// ---------------- K56: trails update + broadcast multiply (one launch) -----
__global__ void __launch_bounds__(256)
k56_finish(const float* __restrict__ trails,
           const float* __restrict__ decay_p,
           const float* __restrict__ x,
           float* __restrict__ out1,
           float* __restrict__ out0) {
    int b = blockIdx.x;
    int tid = threadIdx.x;
    if (b < TRAIL_BLOCKS) {
        float dec = 1.0f - decay_p[0];
        size_t base = (size_t)b * 256 + tid;
        #pragma unroll
        for (int j = 0; j < 2; j++) {
            size_t idx4 = (base + (size_t)j * TRAIL_BLOCKS * 256) * 4;
            int i  = (int)(idx4 >> 11);       // row
            int j0 = (int)(idx4 & (H - 1));
            const float4 t = *reinterpret_cast<const float4*>(trails + idx4);
            float d = g_diag[i];
            float4 o;
            o.x = (t.x + (i == (j0 + 0) ? d : 0.0f)) * dec;
            o.y = (t.y + (i == (j0 + 1) ? d : 0.0f)) * dec;
            o.z = (t.z + (i == (j0 + 2) ? d : 0.0f)) * dec;
            o.w = (t.w + (i == (j0 + 3) ? d : 0.0f)) * dec;
            *reinterpret_cast<float4*>(out1 + idx4) = o;
        }
    } else {
        // x section: 4 float4/thread; skip reading x where bestpath chunk == 0
        size_t base = (size_t)(b - TRAIL_BLOCKS) * 256 + tid;
        #pragma unroll
        for (int j = 0; j < 4; j++) {
            size_t idx4 = (base + (size_t)j * OUT_BLOCKS * 256) * 4;
            int h0 = (int)(idx4 & (H - 1));
            const float4 bp = *reinterpret_cast<const float4*>(g_bestpath + h0);
            float4 o = make_float4(0.0f, 0.0f, 0.0f, 0.0f);
            if (bp.x != 0.0f || bp.y != 0.0f || bp.z != 0.0f || bp.w != 0.0f) {
                const float4 xv = *reinterpret_cast<const float4*>(x + idx4);
                o.x = xv.x * bp.x;
                o.y = xv.y * bp.y;
                o.z = xv.z * bp.z;
                o.w = xv.w * bp.w;
            }
            *reinterpret_cast<float4*>(out0 + idx4) = o;
        }
    }
}

extern "C" void kernel_launch(void* const* d_in, const int* in_sizes, int n_in,
                              void* d_out, int out_size) {
    const float* x        = (const float*)d_in[0];
    const float* trails   = (const float*)d_in[1];
    const float* paths    = (const float*)d_in[2];
    const float* bestpath = (const float*)d_in[3];
    const float* bpl      = (const float*)d_in[4];
    const float* decay    = (const float*)d_in[5];
    const float* strength = (const float*)d_in[6];
    const int*   antpos   = (const int*)d_in[7];
    float* out = (float*)d_out;

    k0_rowstats<<<H, 256>>>(trails);
    k12_sample_paths<<<A, 256>>>(trails, paths, antpos, strength,
                                 out + OUT2, out + OUT4);
    k34_best<<<1, 1024>>>(bpl, bestpath, out + OUT2, out + OUT3);
    k56_finish<<<TRAIL_BLOCKS + OUT_BLOCKS, 256>>>(trails, decay, x,
                                                   out + OUT1, out + OUT0);
}

// round 8
// speedup vs baseline: 1.2779x; 1.0014x over previous
#include <cuda_runtime.h>
#include <cuda_bf16.h>
#include <cstdint>

#define B 8
#define S 2048
#define H 2048
#define A 8192

// output section offsets (element counts, float32)
#define OUT0 0ULL                               // x*best_path  [B*S*H]
#define OUT1 (OUT0 + (size_t)B * S * H)         // new_trails   [H*H]
#define OUT2 (OUT1 + (size_t)H * H)             // new_paths    [A*H]
#define OUT3 (OUT2 + (size_t)A * H)             // new_best_len [1]
#define OUT4 (OUT3 + 1ULL)                      // next_pos     [A] (as f32)

#define TRAIL_BLOCKS (H * H / 4 / 256 / 2)          // 2048 (2 float4/thread)
#define OUT_BLOCKS   ((B * S * H) / 4 / 256 / 4)    // 8192  (4 float4/thread)

// ---------------- device scratch (no allocations allowed) ----------------
__device__ float g_diag[H];
__device__ float g_rowmax[H];
__device__ float g_rowlse[H];
__device__ int   g_rowconst[H];
__device__ unsigned long long g_minkey;   // (len_bits<<32)|ant : atomicMin argmin

// mad.lo with an opaque 'one' (kernel param) -> IMAD on the fma pipe,
// keeping the alu pipe free for threefry's SHF/LOP3.
__device__ __forceinline__ uint32_t madd(uint32_t one, uint32_t a, uint32_t b) {
    uint32_t r;
    asm("mad.lo.s32 %0, %1, %2, %3;" : "=r"(r) : "r"(one), "r"(a), "r"(b));
    return r;
}

// ---------------- threefry2x32, key = (0, 42), adds on fma pipe -----------
__device__ __forceinline__ uint32_t random_bits_partitionable(uint32_t one, uint32_t i) {
    const uint32_t k0 = 0u, k1 = 42u;
    const uint32_t k2 = k0 ^ k1 ^ 0x1BD11BDAu;
    uint32_t x0 = k0, x1 = madd(one, i, k1);
#define TF_R(r) { x0 = madd(one, x1, x0); x1 = __funnelshift_l(x1, x1, (r)); x1 ^= x0; }
    TF_R(13) TF_R(15) TF_R(26) TF_R(6)
    x0 = madd(one, k1, x0); x1 = madd(one, k2 + 1u, x1);
    TF_R(17) TF_R(29) TF_R(16) TF_R(24)
    x0 = madd(one, k2, x0); x1 = madd(one, k0 + 2u, x1);
    TF_R(13) TF_R(15) TF_R(26) TF_R(6)
    x0 = madd(one, k0, x0); x1 = madd(one, k1 + 3u, x1);
    TF_R(17) TF_R(29) TF_R(16) TF_R(24)
    x0 = madd(one, k1, x0); x1 = madd(one, k2 + 4u, x1);
    TF_R(13) TF_R(15) TF_R(26) TF_R(6)
    x0 = madd(one, k2, x0); x1 = madd(one, k0 + 5u, x1);
#undef TF_R
    return x0 ^ x1;
}

__device__ __forceinline__ float gumbel_from_bits(uint32_t bits) {
    float f = __uint_as_float((bits >> 9) | 0x3F800000u) - 1.0f;
    const float tiny = 1.17549435e-38f;
    float u = fmaxf(tiny, f * (1.0f - tiny) + tiny);
    float t = -__logf(u);
    return -__logf(t);
}

// ---------------- K0: row max/lse/const-flag of trails; zero diag ----------
__global__ void k0_rowstats(const float* __restrict__ trails) {
    __shared__ float smax[256];
    __shared__ float smin[256];
    int r = blockIdx.x;
    int tid = threadIdx.x;
    const float4* row4 = reinterpret_cast<const float4*>(trails + (size_t)r * H) + tid * 2;
    float4 v0 = row4[0], v1 = row4[1];
    float m  = fmaxf(fmaxf(fmaxf(v0.x, v0.y), fmaxf(v0.z, v0.w)),
                     fmaxf(fmaxf(v1.x, v1.y), fmaxf(v1.z, v1.w)));
    float mn = fminf(fminf(fminf(v0.x, v0.y), fminf(v0.z, v0.w)),
                     fminf(fminf(v1.x, v1.y), fminf(v1.z, v1.w)));
    smax[tid] = m; smin[tid] = mn; __syncthreads();
    for (int s = 128; s > 0; s >>= 1) {
        if (tid < s) {
            smax[tid] = fmaxf(smax[tid], smax[tid + s]);
            smin[tid] = fminf(smin[tid], smin[tid + s]);
        }
        __syncthreads();
    }
    float rmax = smax[0], rmin = smin[0]; __syncthreads();
    float sum = expf(v0.x - rmax) + expf(v0.y - rmax) + expf(v0.z - rmax) + expf(v0.w - rmax)
              + expf(v1.x - rmax) + expf(v1.y - rmax) + expf(v1.z - rmax) + expf(v1.w - rmax);
    smax[tid] = sum; __syncthreads();
    for (int s = 128; s > 0; s >>= 1) {
        if (tid < s) smax[tid] += smax[tid + s];
        __syncthreads();
    }
    if (tid == 0) {
        g_rowmax[r] = rmax;
        g_rowlse[r] = logf(smax[0]);
        g_rowconst[r] = (rmax == rmin);
        g_diag[r] = 0.0f;
        if (r == 0) g_minkey = ~0ULL;   // reset argmin key each launch
    }
}

// ---------------- K12: fused sampling + paths + lengths + diag + argmin ----
// thread-contiguous layout: thread tid owns h = tid*8 .. tid*8+7
__global__ void __launch_bounds__(256)
k12_sample_paths(const float* __restrict__ trails,
                 const float* __restrict__ ant_paths,
                 const int* __restrict__ ant_positions,
                 const float* __restrict__ strength_p,
                 float* __restrict__ out2,
                 float* __restrict__ out4,
                 uint32_t one) {
    __shared__ float sv[256];
    __shared__ int   si[256];
    __shared__ float ss[256];
    __shared__ float s_upd;
    __shared__ int   s_np;
    int a = blockIdx.x;
    int tid = threadIdx.x;
    int p = ant_positions[a];
    const float* prow = ant_paths + (size_t)a * H;
    float* orow = out2 + (size_t)a * H;

    // path row: 8 contiguous floats per thread, float4 I/O
    const float4* p4 = reinterpret_cast<const float4*>(prow) + tid * 2;
    float4* o4 = reinterpret_cast<float4*>(orow) + tid * 2;
    float4 pv0 = p4[0], pv1 = p4[1];
    o4[0] = pv0; o4[1] = pv1;
    float sumsq = pv0.x * pv0.x + pv0.y * pv0.y + pv0.z * pv0.z + pv0.w * pv0.w
                + pv1.x * pv1.x + pv1.y * pv1.y + pv1.z * pv1.z + pv1.w * pv1.w;
    uint32_t mask = 0;   // bit k <=> prow[tid*8+k] > 0
    if (pv0.x > 0.0f) mask |= 1u;  if (pv0.y > 0.0f) mask |= 2u;
    if (pv0.z > 0.0f) mask |= 4u;  if (pv0.w > 0.0f) mask |= 8u;
    if (pv1.x > 0.0f) mask |= 16u; if (pv1.y > 0.0f) mask |= 32u;
    if (pv1.z > 0.0f) mask |= 64u; if (pv1.w > 0.0f) mask |= 128u;

    float bvf;
    int   bi;
    uint32_t ibase = (uint32_t)a * H + (uint32_t)tid * 8u;

    if (g_rowconst[p]) {
        // constant logits: argmax z == argmax (bits>>9).
        // w = (bits & ~0x1FF) | (7-k): one LOP3; max w == max z with smallest
        // k on z-ties (z fields differ by >=512 > any priority field).
        uint32_t bw = 0u;
        #pragma unroll
        for (uint32_t k = 0; k < 8; k++) {
            uint32_t bits = random_bits_partitionable(one, ibase + k);
            uint32_t w = (bits & 0xFFFFFE00u) | (7u - k);
            bw = max(bw, w);
        }
        bvf = (float)(bw >> 9);               // exact (23-bit)
        bi  = tid * 8 + (int)(7u - (bw & 7u));
    } else {
        const float* trow = trails + (size_t)p * H;
        float rm = g_rowmax[p], rl = g_rowlse[p];
        bvf = -__int_as_float(0x7f800000); bi = 0;
        #pragma unroll
        for (uint32_t k = 0; k < 8; k++) {
            int h = tid * 8 + k;
            uint32_t bits = random_bits_partitionable(one, ibase + k);
            float z = gumbel_from_bits(bits) + ((trow[h] - rm) - rl);
            if (z > bvf) { bvf = z; bi = h; }  // h increasing -> first index kept
        }
    }

    // cross-thread reduce: (z, h) with first-index (smallest h) tie-break
    sv[tid] = bvf; si[tid] = bi; ss[tid] = sumsq; __syncthreads();
    for (int s = 128; s > 0; s >>= 1) {
        if (tid < s) {
            float v2 = sv[tid + s]; int i2 = si[tid + s];
            if (v2 > sv[tid] || (v2 == sv[tid] && i2 < si[tid])) { sv[tid] = v2; si[tid] = i2; }
            ss[tid] += ss[tid + s];
        }
        __syncthreads();
    }
    if (tid == 0) {
        int np = si[0];
        float old = prow[np];
        float len = sqrtf(ss[0] - old * old + 1.0f);   // one-hot substitution
        // global argmin: len>=0 -> float order == uint bit order; low word = ant
        unsigned long long key =
            ((unsigned long long)__float_as_uint(len) << 32) | (unsigned)a;
        atomicMin(&g_minkey, key);
        s_np = np;
        s_upd = strength_p[0] / (len + 1e-8f);
        out4[a] = (float)np;
    }
    __syncthreads();
    float upd = s_upd;
    int np = s_np;
    // sparse diag fixups only (stores already done above)
    if (mask) {
        #pragma unroll
        for (uint32_t k = 0; k < 8; k++)
            if (mask & (1u << k)) atomicAdd(&g_diag[tid * 8 + k], upd);
    }
    if (tid == 0) {
        orow[np] = 1.0f;                       // after __syncthreads: ordered
        if (!(prow[np] > 0.0f)) atomicAdd(&g_diag[np], upd);
    }
}

// ---------------- K56: trails + best-len + broadcast multiply (one launch) -
__global__ void __launch_bounds__(256)
k56_finish(const float* __restrict__ trails,
           const float* __restrict__ decay_p,
           const float* __restrict__ x,
           const float* __restrict__ bpl_p,
           const float* __restrict__ best_path_in,
           const float* __restrict__ new_paths_out,
           float* __restrict__ out1,
           float* __restrict__ out0,
           float* __restrict__ out3) {
    int b = blockIdx.x;
    int tid = threadIdx.x;
    if (b < TRAIL_BLOCKS) {
        float dec = 1.0f - decay_p[0];
        size_t base = (size_t)b * 256 + tid;
        #pragma unroll
        for (int j = 0; j < 2; j++) {
            size_t idx4 = (base + (size_t)j * TRAIL_BLOCKS * 256) * 4;
            int i  = (int)(idx4 >> 11);       // row
            int j0 = (int)(idx4 & (H - 1));
            const float4 t = *reinterpret_cast<const float4*>(trails + idx4);
            float d = g_diag[i];
            float4 o;
            o.x = (t.x + (i == (j0 + 0) ? d : 0.0f)) * dec;
            o.y = (t.y + (i == (j0 + 1) ? d : 0.0f)) * dec;
            o.z = (t.z + (i == (j0 + 2) ? d : 0.0f)) * dec;
            o.w = (t.w + (i == (j0 + 3) ? d : 0.0f)) * dec;
            *reinterpret_cast<float4*>(out1 + idx4) = o;
        }
    } else {
        // resolve best path inline (k34 folded in)
        unsigned long long key = g_minkey;
        float blen = __uint_as_float((unsigned)(key >> 32));
        int   best = (int)(unsigned)(key & 0xFFFFFFFFu);
        float bpl  = bpl_p[0];
        int improved = blen < bpl;
        if (b == TRAIL_BLOCKS && tid == 0) out3[0] = improved ? blen : bpl;
        const float* src = improved ? (new_paths_out + (size_t)best * H)
                                    : best_path_in;   // 8KB, L2-hot broadcast
        size_t base = (size_t)(b - TRAIL_BLOCKS) * 256 + tid;
        #pragma unroll
        for (int j = 0; j < 4; j++) {
            size_t idx4 = (base + (size_t)j * OUT_BLOCKS * 256) * 4;
            int h0 = (int)(idx4 & (H - 1));
            const float4 bp = *reinterpret_cast<const float4*>(src + h0);
            float4 o = make_float4(0.0f, 0.0f, 0.0f, 0.0f);
            if (bp.x != 0.0f || bp.y != 0.0f || bp.z != 0.0f || bp.w != 0.0f) {
                const float4 xv = *reinterpret_cast<const float4*>(x + idx4);
                o.x = xv.x * bp.x;
                o.y = xv.y * bp.y;
                o.z = xv.z * bp.z;
                o.w = xv.w * bp.w;
            }
            *reinterpret_cast<float4*>(out0 + idx4) = o;
        }
    }
}

extern "C" void kernel_launch(void* const* d_in, const int* in_sizes, int n_in,
                              void* d_out, int out_size) {
    const float* x        = (const float*)d_in[0];
    const float* trails   = (const float*)d_in[1];
    const float* paths    = (const float*)d_in[2];
    const float* bestpath = (const float*)d_in[3];
    const float* bpl      = (const float*)d_in[4];
    const float* decay    = (const float*)d_in[5];
    const float* strength = (const float*)d_in[6];
    const int*   antpos   = (const int*)d_in[7];
    float* out = (float*)d_out;

    k0_rowstats<<<H, 256>>>(trails);
    k12_sample_paths<<<A, 256>>>(trails, paths, antpos, strength,
                                 out + OUT2, out + OUT4, 1u);
    k56_finish<<<TRAIL_BLOCKS + OUT_BLOCKS, 256>>>(trails, decay, x, bpl,
                                                   bestpath, out + OUT2,
                                                   out + OUT1, out + OUT0,
                                                   out + OUT3);
}

// round 9
// speedup vs baseline: 1.6325x; 1.2775x over previous
#include <cuda_runtime.h>
#include <cuda_bf16.h>
#include <cstdint>

#define B 8
#define S 2048
#define H 2048
#define A 8192

// output section offsets (element counts, float32)
#define OUT0 0ULL                               // x*best_path  [B*S*H]
#define OUT1 (OUT0 + (size_t)B * S * H)         // new_trails   [H*H]
#define OUT2 (OUT1 + (size_t)H * H)             // new_paths    [A*H]
#define OUT3 (OUT2 + (size_t)A * H)             // new_best_len [1]
#define OUT4 (OUT3 + 1ULL)                      // next_pos     [A] (as f32)

#define TRAIL_BLOCKS (H * H / 4 / 256 / 2)          // 2048 (2 float4/thread)
#define OUT_BLOCKS   ((B * S * H) / 4 / 256 / 4)    // 8192  (4 float4/thread)

// ---------------- device scratch (no allocations allowed) ----------------
__device__ float g_diag[H];
__device__ float g_rowmax[H];
__device__ float g_rowlse[H];
__device__ int   g_rowconst[H];
__device__ unsigned long long g_minkey;   // (len_bits<<32)|ant : atomicMin argmin

// mad.lo with an opaque 'one' (kernel param) -> IMAD on the fma pipe,
// keeping the alu pipe free for threefry's SHF/LOP3.
__device__ __forceinline__ uint32_t madd(uint32_t one, uint32_t a, uint32_t b) {
    uint32_t r;
    asm("mad.lo.s32 %0, %1, %2, %3;" : "=r"(r) : "r"(one), "r"(a), "r"(b));
    return r;
}

// ---------------- threefry2x32, key = (0, 42) (20 rounds) -----------------
__device__ __forceinline__ uint32_t random_bits_partitionable(uint32_t one, uint32_t i) {
    const uint32_t k0 = 0u, k1 = 42u;
    const uint32_t k2 = k0 ^ k1 ^ 0x1BD11BDAu;
    uint32_t x0 = k0, x1 = madd(one, i, k1);
#define TF_R(r) { x0 = madd(one, x1, x0); x1 = __funnelshift_l(x1, x1, (r)); x1 ^= x0; }
    TF_R(13) TF_R(15) TF_R(26) TF_R(6)
    x0 = madd(one, k1, x0); x1 = madd(one, k2 + 1u, x1);
    TF_R(17) TF_R(29) TF_R(16) TF_R(24)
    x0 = madd(one, k2, x0); x1 = madd(one, k0 + 2u, x1);
    TF_R(13) TF_R(15) TF_R(26) TF_R(6)
    x0 = madd(one, k0, x0); x1 = madd(one, k1 + 3u, x1);
    TF_R(17) TF_R(29) TF_R(16) TF_R(24)
    x0 = madd(one, k1, x0); x1 = madd(one, k2 + 4u, x1);
    TF_R(13) TF_R(15) TF_R(26) TF_R(6)
    x0 = madd(one, k2, x0); x1 = madd(one, k0 + 5u, x1);
#undef TF_R
    return x0 ^ x1;
}

__device__ __forceinline__ float gumbel_from_bits(uint32_t bits) {
    float f = __uint_as_float((bits >> 9) | 0x3F800000u) - 1.0f;
    const float tiny = 1.17549435e-38f;
    float u = fmaxf(tiny, f * (1.0f - tiny) + tiny);
    float t = -__logf(u);
    return -__logf(t);
}

// ---------------- K0: warp-per-row max/min; lse ONLY if row non-const ------
// grid = H/8 blocks, 256 threads (8 warps, one row per warp)
__global__ void __launch_bounds__(256)
k0_rowstats(const float* __restrict__ trails) {
    int warp = threadIdx.x >> 5;
    int lane = threadIdx.x & 31;
    int r = blockIdx.x * 8 + warp;
    const float4* row4 = reinterpret_cast<const float4*>(trails + (size_t)r * H);
    float4 v[16];
    #pragma unroll
    for (int k = 0; k < 16; k++) v[k] = row4[lane + 32 * k];
    float m  = -__int_as_float(0x7f800000);
    float mn =  __int_as_float(0x7f800000);
    #pragma unroll
    for (int k = 0; k < 16; k++) {
        m  = fmaxf(m,  fmaxf(fmaxf(v[k].x, v[k].y), fmaxf(v[k].z, v[k].w)));
        mn = fminf(mn, fminf(fminf(v[k].x, v[k].y), fminf(v[k].z, v[k].w)));
    }
    #pragma unroll
    for (int s = 16; s > 0; s >>= 1) {
        m  = fmaxf(m,  __shfl_xor_sync(0xFFFFFFFFu, m,  s));
        mn = fminf(mn, __shfl_xor_sync(0xFFFFFFFFu, mn, s));
    }
    if (lane == 0) {
        g_rowmax[r] = m;
        g_rowconst[r] = (m == mn);
        g_diag[r] = 0.0f;
        if (r == 0) g_minkey = ~0ULL;   // reset argmin key each launch
    }
    if (m != mn) {   // lse needed only for the non-const fallback path
        float sum = 0.0f;
        #pragma unroll
        for (int k = 0; k < 16; k++)
            sum += expf(v[k].x - m) + expf(v[k].y - m)
                 + expf(v[k].z - m) + expf(v[k].w - m);
        #pragma unroll
        for (int s = 16; s > 0; s >>= 1)
            sum += __shfl_xor_sync(0xFFFFFFFFu, sum, s);
        if (lane == 0) g_rowlse[r] = logf(sum);
    }
}

// ---------------- K12: sampling + paths + lengths + diag + zero out0 -------
// thread-contiguous layout: thread tid owns h = tid*8 .. tid*8+7
__global__ void __launch_bounds__(256)
k12_sample_paths(const float* __restrict__ trails,
                 const float* __restrict__ ant_paths,
                 const int* __restrict__ ant_positions,
                 const float* __restrict__ strength_p,
                 float* __restrict__ out2,
                 float* __restrict__ out4,
                 float* __restrict__ out0,
                 uint32_t one) {
    __shared__ float sv[256];
    __shared__ int   si[256];
    __shared__ float ss[256];
    __shared__ float s_upd;
    __shared__ int   s_np;
    int a = blockIdx.x;
    int tid = threadIdx.x;
    int p = ant_positions[a];
    const float* prow = ant_paths + (size_t)a * H;
    float* orow = out2 + (size_t)a * H;

    // zero a 16KB slice of out0 (hidden under this kernel's ALU shadow)
    {
        float4* z4 = reinterpret_cast<float4*>(out0 + (size_t)a * 4096) + tid;
        const float4 zz = make_float4(0.0f, 0.0f, 0.0f, 0.0f);
        #pragma unroll
        for (int j = 0; j < 4; j++) z4[j * 256] = zz;
    }

    // path row: 8 contiguous floats per thread, float4 I/O
    const float4* p4 = reinterpret_cast<const float4*>(prow) + tid * 2;
    float4* o4 = reinterpret_cast<float4*>(orow) + tid * 2;
    float4 pv0 = p4[0], pv1 = p4[1];
    o4[0] = pv0; o4[1] = pv1;
    float sumsq = pv0.x * pv0.x + pv0.y * pv0.y + pv0.z * pv0.z + pv0.w * pv0.w
                + pv1.x * pv1.x + pv1.y * pv1.y + pv1.z * pv1.z + pv1.w * pv1.w;
    uint32_t mask = 0;   // bit k <=> prow[tid*8+k] > 0
    if (pv0.x > 0.0f) mask |= 1u;  if (pv0.y > 0.0f) mask |= 2u;
    if (pv0.z > 0.0f) mask |= 4u;  if (pv0.w > 0.0f) mask |= 8u;
    if (pv1.x > 0.0f) mask |= 16u; if (pv1.y > 0.0f) mask |= 32u;
    if (pv1.z > 0.0f) mask |= 64u; if (pv1.w > 0.0f) mask |= 128u;

    float bvf;
    int   bi;
    uint32_t ibase = (uint32_t)a * H + (uint32_t)tid * 8u;

    if (g_rowconst[p]) {
        // constant logits: argmax z == argmax (bits>>9).
        // w = (bits & ~0x1FF) | (7-k): one LOP3; max w == max z with smallest
        // k on z-ties (z fields differ by >=512 > any priority field).
        uint32_t bw = 0u;
        #pragma unroll
        for (uint32_t k = 0; k < 8; k++) {
            uint32_t bits = random_bits_partitionable(one, ibase + k);
            uint32_t w = (bits & 0xFFFFFE00u) | (7u - k);
            bw = max(bw, w);
        }
        bvf = (float)(bw >> 9);               // exact (23-bit)
        bi  = tid * 8 + (int)(7u - (bw & 7u));
    } else {
        const float* trow = trails + (size_t)p * H;
        float rm = g_rowmax[p], rl = g_rowlse[p];
        bvf = -__int_as_float(0x7f800000); bi = 0;
        #pragma unroll
        for (uint32_t k = 0; k < 8; k++) {
            int h = tid * 8 + k;
            uint32_t bits = random_bits_partitionable(one, ibase + k);
            float z = gumbel_from_bits(bits) + ((trow[h] - rm) - rl);
            if (z > bvf) { bvf = z; bi = h; }  // h increasing -> first index kept
        }
    }

    // cross-thread reduce: (z, h) with first-index (smallest h) tie-break
    sv[tid] = bvf; si[tid] = bi; ss[tid] = sumsq; __syncthreads();
    for (int s = 128; s > 0; s >>= 1) {
        if (tid < s) {
            float v2 = sv[tid + s]; int i2 = si[tid + s];
            if (v2 > sv[tid] || (v2 == sv[tid] && i2 < si[tid])) { sv[tid] = v2; si[tid] = i2; }
            ss[tid] += ss[tid + s];
        }
        __syncthreads();
    }
    if (tid == 0) {
        int np = si[0];
        float old = prow[np];
        float len = sqrtf(ss[0] - old * old + 1.0f);   // one-hot substitution
        // global argmin: len>=0 -> float order == uint bit order; low word = ant
        unsigned long long key =
            ((unsigned long long)__float_as_uint(len) << 32) | (unsigned)a;
        atomicMin(&g_minkey, key);
        s_np = np;
        s_upd = strength_p[0] / (len + 1e-8f);
        out4[a] = (float)np;
    }
    __syncthreads();
    float upd = s_upd;
    int np = s_np;
    // sparse diag fixups only (stores already done above)
    if (mask) {
        #pragma unroll
        for (uint32_t k = 0; k < 8; k++)
            if (mask & (1u << k)) atomicAdd(&g_diag[tid * 8 + k], upd);
    }
    if (tid == 0) {
        orow[np] = 1.0f;                       // after __syncthreads: ordered
        if (!(prow[np] > 0.0f)) atomicAdd(&g_diag[np], upd);
    }
}

// ---------------- K56: trails + best-len + SPARSE broadcast multiply -------
// out0 already zeroed by k12: x-section only touches chunks where bp != 0.
__global__ void __launch_bounds__(256)
k56_finish(const float* __restrict__ trails,
           const float* __restrict__ decay_p,
           const float* __restrict__ x,
           const float* __restrict__ bpl_p,
           const float* __restrict__ best_path_in,
           const float* __restrict__ new_paths_out,
           float* __restrict__ out1,
           float* __restrict__ out0,
           float* __restrict__ out3) {
    int b = blockIdx.x;
    int tid = threadIdx.x;
    if (b < TRAIL_BLOCKS) {
        float dec = 1.0f - decay_p[0];
        size_t base = (size_t)b * 256 + tid;
        #pragma unroll
        for (int j = 0; j < 2; j++) {
            size_t idx4 = (base + (size_t)j * TRAIL_BLOCKS * 256) * 4;
            int i  = (int)(idx4 >> 11);       // row
            int j0 = (int)(idx4 & (H - 1));
            const float4 t = *reinterpret_cast<const float4*>(trails + idx4);
            float d = g_diag[i];
            float4 o;
            o.x = (t.x + (i == (j0 + 0) ? d : 0.0f)) * dec;
            o.y = (t.y + (i == (j0 + 1) ? d : 0.0f)) * dec;
            o.z = (t.z + (i == (j0 + 2) ? d : 0.0f)) * dec;
            o.w = (t.w + (i == (j0 + 3) ? d : 0.0f)) * dec;
            *reinterpret_cast<float4*>(out1 + idx4) = o;
        }
    } else {
        // resolve best path inline
        unsigned long long key = g_minkey;
        float blen = __uint_as_float((unsigned)(key >> 32));
        int   best = (int)(unsigned)(key & 0xFFFFFFFFu);
        float bpl  = bpl_p[0];
        int improved = blen < bpl;
        if (b == TRAIL_BLOCKS && tid == 0) out3[0] = improved ? blen : bpl;
        const float* src = improved ? (new_paths_out + (size_t)best * H)
                                    : best_path_in;   // 8KB, L1/L2-hot broadcast
        size_t base = (size_t)(b - TRAIL_BLOCKS) * 256 + tid;
        #pragma unroll
        for (int j = 0; j < 4; j++) {
            size_t idx4 = (base + (size_t)j * OUT_BLOCKS * 256) * 4;
            int h0 = (int)(idx4 & (H - 1));
            const float4 bp = *reinterpret_cast<const float4*>(src + h0);
            if (bp.x != 0.0f || bp.y != 0.0f || bp.z != 0.0f || bp.w != 0.0f) {
                const float4 xv = *reinterpret_cast<const float4*>(x + idx4);
                float4 o;
                o.x = xv.x * bp.x;
                o.y = xv.y * bp.y;
                o.z = xv.z * bp.z;
                o.w = xv.w * bp.w;
                *reinterpret_cast<float4*>(out0 + idx4) = o;
            }
            // else: out0 chunk already zeroed by k12
        }
    }
}

extern "C" void kernel_launch(void* const* d_in, const int* in_sizes, int n_in,
                              void* d_out, int out_size) {
    const float* x        = (const float*)d_in[0];
    const float* trails   = (const float*)d_in[1];
    const float* paths    = (const float*)d_in[2];
    const float* bestpath = (const float*)d_in[3];
    const float* bpl      = (const float*)d_in[4];
    const float* decay    = (const float*)d_in[5];
    const float* strength = (const float*)d_in[6];
    const int*   antpos   = (const int*)d_in[7];
    float* out = (float*)d_out;

    k0_rowstats<<<H / 8, 256>>>(trails);
    k12_sample_paths<<<A, 256>>>(trails, paths, antpos, strength,
                                 out + OUT2, out + OUT4, out + OUT0, 1u);
    k56_finish<<<TRAIL_BLOCKS + OUT_BLOCKS, 256>>>(trails, decay, x, bpl,
                                                   bestpath, out + OUT2,
                                                   out + OUT1, out + OUT0,
                                                   out + OUT3);
}